// round 1
// baseline (speedup 1.0000x reference)
#include <cuda_runtime.h>
#include <math_constants.h>

// Problem constants
#define BATCH 8
#define SEQ   1024
#define DIM   1024
#define HEADS 16
#define HDIM  64
#define MTOT  (BATCH * SEQ)   // 8192

// Scratch (device globals — allocation-free rule)
__device__ float g_qkv[MTOT * 3 * DIM];   // [8192, 3072]
__device__ float g_att[MTOT * DIM];       // [8192, 1024]

// ---------------------------------------------------------------------------
// SGEMM + bias: C[M,N] = A[M,K] @ W[K,N] + bias[N]
// 128x128 block tile, BK=8, 256 threads, 8x8 microtile (split 4+4 to keep
// float4 smem reads conflict-free).
// ---------------------------------------------------------------------------
__global__ __launch_bounds__(256, 2)
void sgemm_bias(const float* __restrict__ A, const float* __restrict__ W,
                const float* __restrict__ bias, float* __restrict__ C,
                int M, int N, int K)
{
    __shared__ __align__(16) float As[8][128];
    __shared__ __align__(16) float Bs[8][128];

    const int bm = blockIdx.y << 7;
    const int bn = blockIdx.x << 7;
    const int t  = threadIdx.x;
    const int ty = t >> 4;
    const int tx = t & 15;

    const int arow = t >> 1;
    const int acol = (t & 1) << 2;
    const int brow = t >> 5;
    const int bcol = (t & 31) << 2;

    const float* Aptr = A + (size_t)(bm + arow) * K + acol;
    const float* Wptr = W + (size_t)brow * N + bn + bcol;

    float acc[8][8];
#pragma unroll
    for (int i = 0; i < 8; i++)
#pragma unroll
        for (int j = 0; j < 8; j++) acc[i][j] = 0.f;

    for (int k0 = 0; k0 < K; k0 += 8) {
        float4 a4 = *(const float4*)(Aptr + k0);
        float4 b4 = *(const float4*)(Wptr + (size_t)k0 * N);
        As[acol + 0][arow] = a4.x;
        As[acol + 1][arow] = a4.y;
        As[acol + 2][arow] = a4.z;
        As[acol + 3][arow] = a4.w;
        *(float4*)&Bs[brow][bcol] = b4;
        __syncthreads();
#pragma unroll
        for (int kk = 0; kk < 8; kk++) {
            float ra[8], rb[8];
            *(float4*)(ra + 0) = *(float4*)&As[kk][ty * 4];
            *(float4*)(ra + 4) = *(float4*)&As[kk][64 + ty * 4];
            *(float4*)(rb + 0) = *(float4*)&Bs[kk][tx * 4];
            *(float4*)(rb + 4) = *(float4*)&Bs[kk][64 + tx * 4];
#pragma unroll
            for (int i = 0; i < 8; i++)
#pragma unroll
                for (int j = 0; j < 8; j++)
                    acc[i][j] = fmaf(ra[i], rb[j], acc[i][j]);
        }
        __syncthreads();
    }

#pragma unroll
    for (int ih = 0; ih < 2; ih++)
#pragma unroll
        for (int i = 0; i < 4; i++) {
            const int row = bm + ih * 64 + ty * 4 + i;
#pragma unroll
            for (int jh = 0; jh < 2; jh++) {
                const int col = bn + jh * 64 + tx * 4;
                float4 bb = *(const float4*)&bias[col];
                float4 o;
                o.x = acc[ih * 4 + i][jh * 4 + 0] + bb.x;
                o.y = acc[ih * 4 + i][jh * 4 + 1] + bb.y;
                o.z = acc[ih * 4 + i][jh * 4 + 2] + bb.z;
                o.w = acc[ih * 4 + i][jh * 4 + 3] + bb.w;
                *(float4*)&C[(size_t)row * N + col] = o;
            }
        }
}

// ---------------------------------------------------------------------------
// Flash attention (fp32, causal). One block = one (b, h, q-tile of 64 rows).
// 256 threads as 16x16, each owns a 4x4 fragment of the 64x64 S/O tiles.
// Online softmax stats live in registers (shuffle reductions over the 16
// lanes of each row group). Transposed smem tiles use an XOR swizzle so the
// transpose stores don't 16-way bank-conflict.
// ---------------------------------------------------------------------------
#define SW(d, c) ((c) ^ (((((unsigned)(d)) >> 2) & 15u) << 2))

__global__ __launch_bounds__(256, 3)
void flash_attn()
{
    __shared__ __align__(16) float Qs[64][64];   // [d][r], swizzled cols
    __shared__ __align__(16) float KP[64][64];   // K: [d][c] swizzled; then P: [r][c] natural
    __shared__ __align__(16) float Vs[64][64];   // [c][d], natural

    const int qt = blockIdx.x;          // q tile 0..15
    const int bh = blockIdx.y;          // 0..127
    const int b  = bh >> 4;
    const int h  = bh & 15;
    const int t  = threadIdx.x;
    const int ty = t >> 4;
    const int tx = t & 15;

    const float* qbase = g_qkv + (size_t)b * SEQ * 3072 + h * 64;
    const float* kbase = qbase + 1024;
    const float* vbase = qbase + 2048;

    // Load Q (scaled by 1/sqrt(HD)=0.125), transposed into Qs[d][r]
#pragma unroll
    for (int i = 0; i < 4; i++) {
        const int idx = t + i * 256;
        const int r   = idx >> 4;
        const int d4  = (idx & 15) << 2;
        float4 q = *(const float4*)(qbase + (size_t)(qt * 64 + r) * 3072 + d4);
        Qs[d4 + 0][SW(d4 + 0, r)] = q.x * 0.125f;
        Qs[d4 + 1][SW(d4 + 1, r)] = q.y * 0.125f;
        Qs[d4 + 2][SW(d4 + 2, r)] = q.z * 0.125f;
        Qs[d4 + 3][SW(d4 + 3, r)] = q.w * 0.125f;
    }

    float o[4][4];
    float m[4], l[4];
#pragma unroll
    for (int i = 0; i < 4; i++) {
        m[i] = -CUDART_INF_F;
        l[i] = 0.f;
#pragma unroll
        for (int j = 0; j < 4; j++) o[i][j] = 0.f;
    }

    for (int j = 0; j <= qt; j++) {
        __syncthreads();  // previous PV done before K/V overwrite
#pragma unroll
        for (int i = 0; i < 4; i++) {
            const int idx = t + i * 256;
            const int r   = idx >> 4;
            const int d4  = (idx & 15) << 2;
            float4 k = *(const float4*)(kbase + (size_t)(j * 64 + r) * 3072 + d4);
            KP[d4 + 0][SW(d4 + 0, r)] = k.x;
            KP[d4 + 1][SW(d4 + 1, r)] = k.y;
            KP[d4 + 2][SW(d4 + 2, r)] = k.z;
            KP[d4 + 3][SW(d4 + 3, r)] = k.w;
            *(float4*)&Vs[r][d4] =
                *(const float4*)(vbase + (size_t)(j * 64 + r) * 3072 + d4);
        }
        __syncthreads();

        // S = Q K^T (already scaled)
        float s[4][4];
#pragma unroll
        for (int i = 0; i < 4; i++)
#pragma unroll
            for (int jj = 0; jj < 4; jj++) s[i][jj] = 0.f;

#pragma unroll
        for (int d = 0; d < 64; d++) {
            float4 q4 = *(float4*)&Qs[d][SW(d, ty * 4)];
            float4 k4 = *(float4*)&KP[d][SW(d, tx * 4)];
            const float qv[4] = {q4.x, q4.y, q4.z, q4.w};
            const float kv[4] = {k4.x, k4.y, k4.z, k4.w};
#pragma unroll
            for (int i = 0; i < 4; i++)
#pragma unroll
                for (int jj = 0; jj < 4; jj++)
                    s[i][jj] = fmaf(qv[i], kv[jj], s[i][jj]);
        }

        // Causal mask on the diagonal tile
        if (j == qt) {
#pragma unroll
            for (int i = 0; i < 4; i++)
#pragma unroll
                for (int jj = 0; jj < 4; jj++)
                    if (tx * 4 + jj > ty * 4 + i) s[i][jj] = -CUDART_INF_F;
        }

        __syncthreads();  // everyone done reading K from KP before P overwrites it

        // Online softmax per row (16 tx lanes own one row group)
#pragma unroll
        for (int i = 0; i < 4; i++) {
            float mx = fmaxf(fmaxf(s[i][0], s[i][1]), fmaxf(s[i][2], s[i][3]));
#pragma unroll
            for (int off = 1; off < 16; off <<= 1)
                mx = fmaxf(mx, __shfl_xor_sync(0xffffffffu, mx, off));
            const float mn   = fmaxf(m[i], mx);
            const float corr = __expf(m[i] - mn);   // 0 when m[i] == -inf
            float ps = 0.f;
#pragma unroll
            for (int jj = 0; jj < 4; jj++) {
                const float p = __expf(s[i][jj] - mn);
                s[i][jj] = p;
                ps += p;
            }
#pragma unroll
            for (int off = 1; off < 16; off <<= 1)
                ps += __shfl_xor_sync(0xffffffffu, ps, off);
            l[i] = l[i] * corr + ps;
            m[i] = mn;
#pragma unroll
            for (int jj = 0; jj < 4; jj++) o[i][jj] *= corr;
            // stash P (natural layout, float4, conflict-free)
            *(float4*)&KP[ty * 4 + i][tx * 4] =
                make_float4(s[i][0], s[i][1], s[i][2], s[i][3]);
        }
        __syncthreads();

        // O += P @ V
#pragma unroll
        for (int k = 0; k < 64; k++) {
            float4 v4 = *(float4*)&Vs[k][tx * 4];
            const float vv[4] = {v4.x, v4.y, v4.z, v4.w};
            const float p0 = KP[ty * 4 + 0][k];
            const float p1 = KP[ty * 4 + 1][k];
            const float p2 = KP[ty * 4 + 2][k];
            const float p3 = KP[ty * 4 + 3][k];
#pragma unroll
            for (int jj = 0; jj < 4; jj++) {
                o[0][jj] = fmaf(p0, vv[jj], o[0][jj]);
                o[1][jj] = fmaf(p1, vv[jj], o[1][jj]);
                o[2][jj] = fmaf(p2, vv[jj], o[2][jj]);
                o[3][jj] = fmaf(p3, vv[jj], o[3][jj]);
            }
        }
    }

    // Normalize and write to g_att in [B, T, H*HD] layout
#pragma unroll
    for (int i = 0; i < 4; i++) {
        const float inv = 1.f / l[i];
        const size_t row = (size_t)b * SEQ + qt * 64 + ty * 4 + i;
        *(float4*)&g_att[row * DIM + h * 64 + tx * 4] =
            make_float4(o[i][0] * inv, o[i][1] * inv, o[i][2] * inv, o[i][3] * inv);
    }
}

// ---------------------------------------------------------------------------
extern "C" void kernel_launch(void* const* d_in, const int* in_sizes, int n_in,
                              void* d_out, int out_size)
{
    const float* x      = (const float*)d_in[0];
    const float* w_qkv  = (const float*)d_in[1];
    const float* b_qkv  = (const float*)d_in[2];
    const float* w_proj = (const float*)d_in[3];
    const float* b_proj = (const float*)d_in[4];
    float* out = (float*)d_out;

    float *qkv_ptr, *att_ptr;
    cudaGetSymbolAddress((void**)&qkv_ptr, g_qkv);
    cudaGetSymbolAddress((void**)&att_ptr, g_att);

    dim3 blk(256);
    // 1) QKV projection: [8192,1024] @ [1024,3072] + b_qkv
    sgemm_bias<<<dim3(3 * DIM / 128, MTOT / 128), blk>>>(
        x, w_qkv, b_qkv, qkv_ptr, MTOT, 3 * DIM, DIM);
    // 2) Causal flash attention over the packed qkv buffer
    flash_attn<<<dim3(SEQ / 64, BATCH * HEADS), blk>>>();
    // 3) Output projection: [8192,1024] @ [1024,1024] + b_proj
    sgemm_bias<<<dim3(DIM / 128, MTOT / 128), blk>>>(
        att_ptr, w_proj, b_proj, out, MTOT, DIM, DIM);
}